// round 1
// baseline (speedup 1.0000x reference)
#include <cuda_runtime.h>
#include <math.h>

// Problem dims
#define N_ROWS 4096
#define C_DIM  1024
#define D_ROOT 2002
#define H0     256
#define D0     8000
#define H1     64
#define D1     40257

#define NT_ROOT 16   // ceil(2002/128)
#define NT0     63   // ceil(8000/128)
#define NT1     315  // ceil(40257/128)

// Scratch (allocation-free: __device__ globals)
__device__ float g_h0[N_ROWS * H0];
__device__ float g_h1[N_ROWS * H1];
__device__ float g_part_root[N_ROWS * NT_ROOT];
__device__ float g_part0[N_ROWS * NT0];
__device__ float g_part1[(size_t)N_ROWS * NT1];
__device__ float g_picked[3 * N_ROWS];
__device__ float g_ce[3 * N_ROWS];

// ---------------------------------------------------------------------------
// Fused tiled GEMM. EXPSUM=true: out[row*ntiles + tileCol] = sum_c exp(acc)
// (masked to c < D). EXPSUM=false: plain store of acc to out[row*D + col].
// Tile: BM=64 rows x BN=128 cols, BK=16, 256 threads, 8x4 per-thread microtile.
// Warp w owns rows w*8..w*8+7 and all 128 cols -> row-sum is a warp shuffle.
// ---------------------------------------------------------------------------
template <bool EXPSUM>
__global__ __launch_bounds__(256)
void gemm_fused(const float* __restrict__ X, const float* __restrict__ W,
                float* __restrict__ out, int K, int D, int ntiles)
{
    const int BM = 64, BN = 128, BK = 16;
    __shared__ float Xs[BK][BM + 4];   // transposed X tile (+4 pad, keeps 16B align)
    __shared__ float Ws[BK][BN];

    const int tid  = threadIdx.x;
    const int lane = tid & 31;    // column group within warp
    const int wrow = tid >> 5;    // warp id = row group (0..7)
    const int row0 = blockIdx.y * BM;
    const int col0 = blockIdx.x * BN;

    float acc[8][4];
#pragma unroll
    for (int i = 0; i < 8; i++)
#pragma unroll
        for (int j = 0; j < 4; j++) acc[i][j] = 0.f;

    const int xr = tid >> 2;          // 0..63
    const int xk = (tid & 3) << 2;    // 0,4,8,12

    for (int k0 = 0; k0 < K; k0 += BK) {
        // X tile: one float4 per thread (K is always a multiple of 4 -> aligned)
        float4 xv = *reinterpret_cast<const float4*>(
            X + (size_t)(row0 + xr) * K + k0 + xk);
        Xs[xk + 0][xr] = xv.x;
        Xs[xk + 1][xr] = xv.y;
        Xs[xk + 2][xr] = xv.z;
        Xs[xk + 3][xr] = xv.w;

        // W tile: 8 scalar coalesced loads per thread (D may be odd -> no vec)
#pragma unroll
        for (int i = 0; i < 8; i++) {
            int idx = tid + i * 256;
            int wr  = idx >> 7;        // 0..15
            int wc  = idx & 127;       // 0..127
            int gc  = col0 + wc;
            Ws[wr][wc] = (gc < D) ? W[(size_t)(k0 + wr) * D + gc] : 0.f;
        }
        __syncthreads();

#pragma unroll
        for (int kk = 0; kk < BK; kk++) {
            float4 a0 = *reinterpret_cast<const float4*>(&Xs[kk][wrow * 8]);
            float4 a1 = *reinterpret_cast<const float4*>(&Xs[kk][wrow * 8 + 4]);
            float4 bv = *reinterpret_cast<const float4*>(&Ws[kk][lane * 4]);
            float a[8] = {a0.x, a0.y, a0.z, a0.w, a1.x, a1.y, a1.z, a1.w};
            float b[4] = {bv.x, bv.y, bv.z, bv.w};
#pragma unroll
            for (int i = 0; i < 8; i++)
#pragma unroll
                for (int j = 0; j < 4; j++)
                    acc[i][j] = fmaf(a[i], b[j], acc[i][j]);
        }
        __syncthreads();
    }

    if (EXPSUM) {
#pragma unroll
        for (int i = 0; i < 8; i++) {
            float s = 0.f;
#pragma unroll
            for (int j = 0; j < 4; j++) {
                int gc = col0 + lane * 4 + j;
                s += (gc < D) ? __expf(acc[i][j]) : 0.f;
            }
#pragma unroll
            for (int off = 16; off > 0; off >>= 1)
                s += __shfl_xor_sync(0xffffffffu, s, off);
            if (lane == 0)
                out[(size_t)(row0 + wrow * 8 + i) * ntiles + blockIdx.x] = s;
        }
    } else {
#pragma unroll
        for (int i = 0; i < 8; i++) {
            int gr = row0 + wrow * 8 + i;
            int gc = col0 + lane * 4;
            if (gc + 3 < D) {
                float4 v = make_float4(acc[i][0], acc[i][1], acc[i][2], acc[i][3]);
                *reinterpret_cast<float4*>(out + (size_t)gr * D + gc) = v;
            } else {
#pragma unroll
                for (int j = 0; j < 4; j++)
                    if (gc + j < D) out[(size_t)gr * D + gc + j] = acc[i][j];
            }
        }
    }
}

// ---------------------------------------------------------------------------
// Picked logits: one block per row, three dot products against target columns.
// ---------------------------------------------------------------------------
__global__ __launch_bounds__(128)
void picked_kernel(const float* __restrict__ logits, const int* __restrict__ targets,
                   const float* __restrict__ head_kernel,
                   const float* __restrict__ scale0, const float* __restrict__ scale1)
{
    int n   = blockIdx.x;
    int tid = threadIdx.x;
    int t   = targets[n];
    int rt  = (t < 2000) ? t : ((t < 10000) ? 2000 : 2001);
    int t0  = min(max(t - 2000, 0), D0 - 1);
    int t1  = min(max(t - 10000, 0), D1 - 1);

    float sr = 0.f, s0 = 0.f, s1 = 0.f;
    for (int k = tid; k < C_DIM; k += 128)
        sr += logits[(size_t)n * C_DIM + k] * head_kernel[(size_t)k * D_ROOT + rt];
    for (int k = tid; k < H0; k += 128)
        s0 += g_h0[(size_t)n * H0 + k] * scale0[(size_t)k * D0 + t0];
    if (tid < H1)
        s1 = g_h1[(size_t)n * H1 + tid] * scale1[(size_t)tid * D1 + t1];

    __shared__ float sh[3][128];
    sh[0][tid] = sr; sh[1][tid] = s0; sh[2][tid] = s1;
    __syncthreads();
    for (int off = 64; off > 0; off >>= 1) {
        if (tid < off) {
            sh[0][tid] += sh[0][tid + off];
            sh[1][tid] += sh[1][tid + off];
            sh[2][tid] += sh[2][tid + off];
        }
        __syncthreads();
    }
    if (tid == 0) {
        g_picked[n]              = sh[0][0];
        g_picked[N_ROWS + n]     = sh[1][0];
        g_picked[2 * N_ROWS + n] = sh[2][0];
    }
}

// ---------------------------------------------------------------------------
// Per-row LSE + CE: one block per row, warp 0/1/2 handle root/tail0/tail1.
// ---------------------------------------------------------------------------
__global__ __launch_bounds__(96)
void lse_kernel()
{
    int n    = blockIdx.x;
    int w    = threadIdx.x >> 5;
    int lane = threadIdx.x & 31;

    const float* part;
    int nt;
    if (w == 0)      { part = &g_part_root[(size_t)n * NT_ROOT]; nt = NT_ROOT; }
    else if (w == 1) { part = &g_part0[(size_t)n * NT0];         nt = NT0; }
    else             { part = &g_part1[(size_t)n * NT1];         nt = NT1; }

    float s = 0.f;
    for (int k = lane; k < nt; k += 32) s += part[k];
#pragma unroll
    for (int off = 16; off > 0; off >>= 1)
        s += __shfl_xor_sync(0xffffffffu, s, off);
    if (lane == 0)
        g_ce[w * N_ROWS + n] = logf(s) - g_picked[w * N_ROWS + n];
}

// ---------------------------------------------------------------------------
// Final scalar: masked means over rows, mean of the three losses.
// ---------------------------------------------------------------------------
__global__ __launch_bounds__(1024)
void final_kernel(const int* __restrict__ targets, float* __restrict__ out)
{
    int tid = threadIdx.x;
    float sr = 0.f, s0 = 0.f, c0 = 0.f, s1 = 0.f, c1 = 0.f;
    for (int n = tid; n < N_ROWS; n += 1024) {
        sr += g_ce[n];
        int t = targets[n];
        if (t >= 2000 && t < 10000) { s0 += g_ce[N_ROWS + n];     c0 += 1.f; }
        if (t >= 10000)             { s1 += g_ce[2 * N_ROWS + n]; c1 += 1.f; }
    }
    __shared__ float sh[5][1024];
    sh[0][tid] = sr; sh[1][tid] = s0; sh[2][tid] = c0; sh[3][tid] = s1; sh[4][tid] = c1;
    __syncthreads();
    for (int off = 512; off > 0; off >>= 1) {
        if (tid < off) {
#pragma unroll
            for (int q = 0; q < 5; q++) sh[q][tid] += sh[q][tid + off];
        }
        __syncthreads();
    }
    if (tid == 0) {
        float root_loss = sh[0][0] / (float)N_ROWS;
        float l0 = sh[1][0] / fmaxf(sh[2][0], 1.f);
        float l1 = sh[3][0] / fmaxf(sh[4][0], 1.f);
        out[0] = (root_loss + l0 + l1) / 3.f;
    }
}

// ---------------------------------------------------------------------------
extern "C" void kernel_launch(void* const* d_in, const int* in_sizes, int n_in,
                              void* d_out, int out_size)
{
    const float* logits      = (const float*)d_in[0];
    const int*   targets     = (const int*)  d_in[1];
    const float* head_kernel = (const float*)d_in[2];
    const float* proj0       = (const float*)d_in[3];
    const float* scale0      = (const float*)d_in[4];
    const float* proj1       = (const float*)d_in[5];
    const float* scale1      = (const float*)d_in[6];
    float* out = (float*)d_out;

    float *h0p, *h1p, *prp, *p0p, *p1p;
    cudaGetSymbolAddress((void**)&h0p, g_h0);
    cudaGetSymbolAddress((void**)&h1p, g_h1);
    cudaGetSymbolAddress((void**)&prp, g_part_root);
    cudaGetSymbolAddress((void**)&p0p, g_part0);
    cudaGetSymbolAddress((void**)&p1p, g_part1);

    dim3 blk(256);

    // Tail hidden projections: h0 = logits@proj0, h1 = logits@proj1
    gemm_fused<false><<<dim3(2,  N_ROWS / 64), blk>>>(logits, proj0, h0p, C_DIM, H0, 2);
    gemm_fused<false><<<dim3(1,  N_ROWS / 64), blk>>>(logits, proj1, h1p, C_DIM, H1, 1);

    // Fused GEMM + exp + tile row-sum partials
    gemm_fused<true><<<dim3(NT_ROOT, N_ROWS / 64), blk>>>(logits, head_kernel, prp, C_DIM, D_ROOT, NT_ROOT);
    gemm_fused<true><<<dim3(NT0,     N_ROWS / 64), blk>>>(h0p,    scale0,      p0p, H0,    D0,     NT0);
    gemm_fused<true><<<dim3(NT1,     N_ROWS / 64), blk>>>(h1p,    scale1,      p1p, H1,    D1,     NT1);

    // Picked logits at (remapped) targets
    picked_kernel<<<N_ROWS, 128>>>(logits, targets, head_kernel, scale0, scale1);

    // Per-row LSE and CE
    lse_kernel<<<N_ROWS, 96>>>();

    // Final masked means -> scalar
    final_kernel<<<1, 1024>>>(targets, out);
}

// round 3
// speedup vs baseline: 4.6929x; 4.6929x over previous
#include <cuda_runtime.h>
#include <cuda_bf16.h>
#include <math.h>
#include <stdint.h>

// ---------------- problem dims ----------------
#define N_ROWS 4096
#define C_DIM  1024
#define D_ROOT 2002
#define H0     256
#define H1     64
#define D0     8000
#define D1     40257

#define NT_ROOT 16   // ceil(2002/128)
#define NT0     63
#define NT1     315
#define DPAD_ROOT (NT_ROOT*128)
#define DPAD0     (NT0*128)
#define DPAD1     (NT1*128)

// ---------------- scratch (__device__ globals) ----------------
__device__ __nv_bfloat16 g_xbf[N_ROWS * C_DIM];
__device__ __nv_bfloat16 g_h0bf[N_ROWS * H0];
__device__ __nv_bfloat16 g_h1bf[N_ROWS * H1];
__device__ __nv_bfloat16 g_wtroot[DPAD_ROOT * C_DIM];
__device__ __nv_bfloat16 g_wt0[DPAD0 * H0];
__device__ __nv_bfloat16 g_wt1[(size_t)DPAD1 * H1];
__device__ __nv_bfloat16 g_p0t[H0 * C_DIM];
__device__ __nv_bfloat16 g_p1t[128 * C_DIM];      // proj1^T padded 64->128 rows
__device__ float g_part_root[N_ROWS * NT_ROOT];
__device__ float g_part0[N_ROWS * NT0];
__device__ float g_part1[(size_t)N_ROWS * NT1];
__device__ float g_picked[3 * N_ROWS];
__device__ float g_ce[3 * N_ROWS];

// ---------------- helpers ----------------
static __device__ __forceinline__ uint32_t smem_u32(const void* p) {
    uint32_t r;
    asm("{ .reg .u64 t; cvta.to.shared.u64 t, %1; cvt.u32.u64 %0, t; }" : "=r"(r) : "l"(p));
    return r;
}
static __device__ __forceinline__ void cp_async16(uint32_t dst, const void* src) {
    asm volatile("cp.async.cg.shared.global [%0], [%1], 16;" :: "r"(dst), "l"(src));
}
#define CP_COMMIT()  asm volatile("cp.async.commit_group;")
#define CP_WAIT1()   asm volatile("cp.async.wait_group 1;")

#define LDSM4(r0, r1, r2, r3, addr) \
    asm volatile("ldmatrix.sync.aligned.m8n8.x4.shared.b16 {%0,%1,%2,%3}, [%4];" \
        : "=r"(r0), "=r"(r1), "=r"(r2), "=r"(r3) : "r"(addr))

#define MMA16816(d, a, b0, b1) \
    asm volatile("mma.sync.aligned.m16n8k16.row.col.f32.bf16.bf16.f32 " \
        "{%0,%1,%2,%3}, {%4,%5,%6,%7}, {%8,%9}, {%0,%1,%2,%3};" \
        : "+f"((d)[0]), "+f"((d)[1]), "+f"((d)[2]), "+f"((d)[3]) \
        : "r"((a)[0]), "r"((a)[1]), "r"((a)[2]), "r"((a)[3]), "r"(b0), "r"(b1))

// ---------------- prep kernels ----------------
__global__ __launch_bounds__(256)
void f32_to_bf16_vec(const float* __restrict__ in, __nv_bfloat16* __restrict__ out, int n4)
{
    int i = blockIdx.x * blockDim.x + threadIdx.x;
    if (i < n4) {
        float4 v = reinterpret_cast<const float4*>(in)[i];
        __nv_bfloat162 ab = __floats2bfloat162_rn(v.x, v.y);
        __nv_bfloat162 cd = __floats2bfloat162_rn(v.z, v.w);
        reinterpret_cast<__nv_bfloat162*>(out)[2 * i]     = ab;
        reinterpret_cast<__nv_bfloat162*>(out)[2 * i + 1] = cd;
    }
}

// W [K, D] fp32 -> Wt [Dpad, K] bf16 (rows >= D zero-padded).
__global__ __launch_bounds__(256)
void transpose_f32_bf16(const float* __restrict__ W, __nv_bfloat16* __restrict__ Wt,
                        int K, int D, int Dpad)
{
    __shared__ float sh[32][33];
    int tx = threadIdx.x, ty = threadIdx.y;   // (32, 8)
    int d0 = blockIdx.x * 32, k0 = blockIdx.y * 32;
#pragma unroll
    for (int i = 0; i < 4; i++) {
        int k = k0 + ty + i * 8;
        int d = d0 + tx;
        sh[ty + i * 8][tx] = (d < D) ? W[(size_t)k * D + d] : 0.f;
    }
    __syncthreads();
#pragma unroll
    for (int i = 0; i < 4; i++) {
        int drow = d0 + ty + i * 8;
        int kk   = k0 + tx;
        Wt[(size_t)drow * K + kk] = __float2bfloat16(sh[tx][ty + i * 8]);
    }
}

// ---------------- HMMA bf16 GEMM, 128x128 tile, fused epilogue ----------------
// C = A[rows,K] @ Wt[Dpad,K]^T. EXPSUM=1: row-sums of masked exp -> part.
// EXPSUM=0: bf16 store to outs (cols < D).
// 256 threads = 8 warps, warp grid 2(m) x 4(n), warp tile 64x32.
// SMEM tile: 128 rows x 64 bf16 (128B/row), chunk swizzle c^=(row&7).

#define TILE_BYTES 16384
#define STAGE_BYTES (2 * TILE_BYTES)

template<int EXPSUM>
__global__ void __launch_bounds__(256)
hmma_gemm(const __nv_bfloat16* __restrict__ A, const __nv_bfloat16* __restrict__ B,
          float* __restrict__ part, __nv_bfloat16* __restrict__ outs,
          int K, int D, int ntiles, int ldout)
{
    __shared__ __align__(1024) char smem[2 * STAGE_BYTES];   // 64KB: 2 stages x (A,B)
    const int tid = threadIdx.x;
    const int lane = tid & 31, wid = tid >> 5;
    const int warp_m = wid & 1, warp_n = wid >> 1;
    const int row0 = blockIdx.y << 7, col0 = blockIdx.x << 7;
    const uint32_t sBase = smem_u32(smem);

    float acc[4][4][4];
#pragma unroll
    for (int i = 0; i < 4; i++)
#pragma unroll
        for (int j = 0; j < 4; j++)
#pragma unroll
            for (int q = 0; q < 4; q++) acc[i][j][q] = 0.f;

    // loader indices: 1024 16B chunks, 4 per thread
    const int lr = tid >> 1;                 // will re-derive per i
    (void)lr;

    auto load_stage = [&](int stage, int kt) {
        const uint32_t sA = sBase + stage * STAGE_BYTES;
        const uint32_t sB = sA + TILE_BYTES;
        const int k0 = kt << 6;
#pragma unroll
        for (int i = 0; i < 4; i++) {
            int c  = tid + (i << 8);
            int r  = c >> 3, kc = c & 7;
            uint32_t off = (uint32_t)(r << 7) + (uint32_t)((kc ^ (r & 7)) << 4);
            cp_async16(sA + off, A + (size_t)(row0 + r) * K + k0 + (kc << 3));
            cp_async16(sB + off, B + (size_t)(col0 + r) * K + k0 + (kc << 3));
        }
    };

    // ldmatrix per-lane addressing
    const int lane7 = lane & 7;
    const int b3 = (lane >> 3) & 1, b4 = (lane >> 4) & 1;
    const uint32_t aRowOff = (uint32_t)((warp_m * 64 + lane7 + 8 * b3) << 7);
    const uint32_t bRowOff = (uint32_t)((warp_n * 32 + lane7 + 8 * b3) << 7);

    const int nk = K >> 6;
    load_stage(0, 0);
    CP_COMMIT();
    if (nk > 1) load_stage(1, 1);
    CP_COMMIT();

    for (int kt = 0; kt < nk; kt++) {
        CP_WAIT1();
        __syncthreads();
        const uint32_t sA = sBase + (kt & 1) * STAGE_BYTES;
        const uint32_t sB = sA + TILE_BYTES;
#pragma unroll
        for (int ks = 0; ks < 4; ks++) {
            uint32_t a[4][4], b[2][4];
            const uint32_t chunk = (uint32_t)((((ks << 1) + b4) ^ lane7) << 4);
#pragma unroll
            for (int mt = 0; mt < 4; mt++)
                LDSM4(a[mt][0], a[mt][1], a[mt][2], a[mt][3],
                      sA + aRowOff + (uint32_t)(mt << 11) + chunk);
#pragma unroll
            for (int np = 0; np < 2; np++)
                LDSM4(b[np][0], b[np][1], b[np][2], b[np][3],
                      sB + bRowOff + (uint32_t)(np << 11) + chunk);
#pragma unroll
            for (int mt = 0; mt < 4; mt++) {
#pragma unroll
                for (int np = 0; np < 2; np++) {
                    MMA16816(acc[mt][2 * np],     a[mt], b[np][0], b[np][2]);
                    MMA16816(acc[mt][2 * np + 1], a[mt], b[np][1], b[np][3]);
                }
            }
        }
        __syncthreads();
        if (kt + 2 < nk) load_stage(kt & 1, kt + 2);
        CP_COMMIT();
    }

    // ---- epilogue ----
    if (EXPSUM) {
        float* red = reinterpret_cast<float*>(smem);  // [128][4]
        const int cb = col0 + warp_n * 32 + 2 * (lane & 3);
#pragma unroll
        for (int mt = 0; mt < 4; mt++) {
#pragma unroll
            for (int h = 0; h < 2; h++) {
                float p = 0.f;
#pragma unroll
                for (int nt = 0; nt < 4; nt++) {
                    int gc = cb + nt * 8;
                    float v0 = acc[mt][nt][2 * h], v1 = acc[mt][nt][2 * h + 1];
                    if (gc < D)     p += __expf(v0);
                    if (gc + 1 < D) p += __expf(v1);
                }
                p += __shfl_xor_sync(0xffffffffu, p, 1);
                p += __shfl_xor_sync(0xffffffffu, p, 2);
                if ((lane & 3) == 0) {
                    int r = warp_m * 64 + mt * 16 + (lane >> 2) + 8 * h;
                    red[r * 4 + warp_n] = p;
                }
            }
        }
        __syncthreads();
        if (tid < 128) {
            float s = red[tid * 4] + red[tid * 4 + 1] + red[tid * 4 + 2] + red[tid * 4 + 3];
            part[(size_t)(row0 + tid) * ntiles + blockIdx.x] = s;
        }
    } else {
#pragma unroll
        for (int mt = 0; mt < 4; mt++) {
#pragma unroll
            for (int h = 0; h < 2; h++) {
                int row = row0 + warp_m * 64 + mt * 16 + (lane >> 2) + 8 * h;
#pragma unroll
                for (int nt = 0; nt < 4; nt++) {
                    int gc = col0 + warp_n * 32 + nt * 8 + 2 * (lane & 3);
                    if (gc < D) {
                        __nv_bfloat162 v = __floats2bfloat162_rn(acc[mt][nt][2 * h],
                                                                 acc[mt][nt][2 * h + 1]);
                        *reinterpret_cast<__nv_bfloat162*>(outs + (size_t)row * ldout + gc) = v;
                    }
                }
            }
        }
    }
}

// ---------------- picked logits ----------------
__global__ __launch_bounds__(128)
void picked_kernel(const float* __restrict__ logits, const int* __restrict__ targets,
                   const float* __restrict__ head_kernel,
                   const float* __restrict__ scale0, const float* __restrict__ scale1)
{
    int n   = blockIdx.x;
    int tid = threadIdx.x;
    int t   = targets[n];
    int rt  = (t < 2000) ? t : ((t < 10000) ? 2000 : 2001);
    int t0  = min(max(t - 2000, 0), D0 - 1);
    int t1  = min(max(t - 10000, 0), D1 - 1);

    float sr = 0.f, s0 = 0.f, s1 = 0.f;
    for (int k = tid; k < C_DIM; k += 128)
        sr += logits[(size_t)n * C_DIM + k] * head_kernel[(size_t)k * D_ROOT + rt];
    for (int k = tid; k < H0; k += 128)
        s0 += __bfloat162float(g_h0bf[(size_t)n * H0 + k]) * scale0[(size_t)k * D0 + t0];
    if (tid < H1)
        s1 = __bfloat162float(g_h1bf[(size_t)n * H1 + tid]) * scale1[(size_t)tid * D1 + t1];

    __shared__ float sh[3][128];
    sh[0][tid] = sr; sh[1][tid] = s0; sh[2][tid] = s1;
    __syncthreads();
    for (int off = 64; off > 0; off >>= 1) {
        if (tid < off) {
            sh[0][tid] += sh[0][tid + off];
            sh[1][tid] += sh[1][tid + off];
            sh[2][tid] += sh[2][tid + off];
        }
        __syncthreads();
    }
    if (tid == 0) {
        g_picked[n]              = sh[0][0];
        g_picked[N_ROWS + n]     = sh[1][0];
        g_picked[2 * N_ROWS + n] = sh[2][0];
    }
}

// ---------------- LSE + CE ----------------
__global__ __launch_bounds__(96)
void lse_kernel()
{
    int n    = blockIdx.x;
    int w    = threadIdx.x >> 5;
    int lane = threadIdx.x & 31;

    const float* part;
    int nt;
    if (w == 0)      { part = &g_part_root[(size_t)n * NT_ROOT]; nt = NT_ROOT; }
    else if (w == 1) { part = &g_part0[(size_t)n * NT0];         nt = NT0; }
    else             { part = &g_part1[(size_t)n * NT1];         nt = NT1; }

    float s = 0.f;
    for (int k = lane; k < nt; k += 32) s += part[k];
#pragma unroll
    for (int off = 16; off > 0; off >>= 1)
        s += __shfl_xor_sync(0xffffffffu, s, off);
    if (lane == 0)
        g_ce[w * N_ROWS + n] = logf(s) - g_picked[w * N_ROWS + n];
}

// ---------------- final scalar ----------------
__global__ __launch_bounds__(1024)
void final_kernel(const int* __restrict__ targets, float* __restrict__ out)
{
    int tid = threadIdx.x;
    float sr = 0.f, s0 = 0.f, c0 = 0.f, s1 = 0.f, c1 = 0.f;
    for (int n = tid; n < N_ROWS; n += 1024) {
        sr += g_ce[n];
        int t = targets[n];
        if (t >= 2000 && t < 10000) { s0 += g_ce[N_ROWS + n];     c0 += 1.f; }
        if (t >= 10000)             { s1 += g_ce[2 * N_ROWS + n]; c1 += 1.f; }
    }
    __shared__ float sh[5][1024];
    sh[0][tid] = sr; sh[1][tid] = s0; sh[2][tid] = c0; sh[3][tid] = s1; sh[4][tid] = c1;
    __syncthreads();
    for (int off = 512; off > 0; off >>= 1) {
        if (tid < off) {
#pragma unroll
            for (int q = 0; q < 5; q++) sh[q][tid] += sh[q][tid + off];
        }
        __syncthreads();
    }
    if (tid == 0) {
        float root_loss = sh[0][0] / (float)N_ROWS;
        float l0 = sh[1][0] / fmaxf(sh[2][0], 1.f);
        float l1 = sh[3][0] / fmaxf(sh[4][0], 1.f);
        out[0] = (root_loss + l0 + l1) / 3.f;
    }
}

// ---------------- host launch ----------------
extern "C" void kernel_launch(void* const* d_in, const int* in_sizes, int n_in,
                              void* d_out, int out_size)
{
    const float* logits      = (const float*)d_in[0];
    const int*   targets     = (const int*)  d_in[1];
    const float* head_kernel = (const float*)d_in[2];
    const float* proj0       = (const float*)d_in[3];
    const float* scale0      = (const float*)d_in[4];
    const float* proj1       = (const float*)d_in[5];
    const float* scale1      = (const float*)d_in[6];
    float* out = (float*)d_out;

    __nv_bfloat16 *xbf, *h0bf, *h1bf, *wtroot, *wt0, *wt1, *p0t, *p1t;
    float *prp, *p0p, *p1p;
    cudaGetSymbolAddress((void**)&xbf,    g_xbf);
    cudaGetSymbolAddress((void**)&h0bf,   g_h0bf);
    cudaGetSymbolAddress((void**)&h1bf,   g_h1bf);
    cudaGetSymbolAddress((void**)&wtroot, g_wtroot);
    cudaGetSymbolAddress((void**)&wt0,    g_wt0);
    cudaGetSymbolAddress((void**)&wt1,    g_wt1);
    cudaGetSymbolAddress((void**)&p0t,    g_p0t);
    cudaGetSymbolAddress((void**)&p1t,    g_p1t);
    cudaGetSymbolAddress((void**)&prp,    g_part_root);
    cudaGetSymbolAddress((void**)&p0p,    g_part0);
    cudaGetSymbolAddress((void**)&p1p,    g_part1);

    // 1. fp32 -> bf16 conversions / transposes
    f32_to_bf16_vec<<<(N_ROWS * C_DIM / 4 + 255) / 256, 256>>>(logits, xbf, N_ROWS * C_DIM / 4);
    transpose_f32_bf16<<<dim3(DPAD_ROOT / 32, C_DIM / 32), dim3(32, 8)>>>(head_kernel, wtroot, C_DIM, D_ROOT, DPAD_ROOT);
    transpose_f32_bf16<<<dim3(H0 / 32,        C_DIM / 32), dim3(32, 8)>>>(proj0,       p0t,    C_DIM, H0,     H0);
    transpose_f32_bf16<<<dim3(DPAD0 / 32,     H0 / 32),    dim3(32, 8)>>>(scale0,      wt0,    H0,    D0,     DPAD0);
    transpose_f32_bf16<<<dim3(128 / 32,       C_DIM / 32), dim3(32, 8)>>>(proj1,       p1t,    C_DIM, H1,     128);
    transpose_f32_bf16<<<dim3(DPAD1 / 32,     H1 / 32),    dim3(32, 8)>>>(scale1,      wt1,    H1,    D1,     DPAD1);

    // 2. tail hidden projections (HMMA, bf16 store)
    hmma_gemm<0><<<dim3(2, N_ROWS / 128), 256>>>(xbf, p0t, nullptr, h0bf, C_DIM, H0, 0, H0);
    hmma_gemm<0><<<dim3(1, N_ROWS / 128), 256>>>(xbf, p1t, nullptr, h1bf, C_DIM, H1, 0, H1);

    // 3. fused GEMM + exp + per-tile row-sum partials (HMMA)
    hmma_gemm<1><<<dim3(NT_ROOT, N_ROWS / 128), 256>>>(xbf,  wtroot, prp, nullptr, C_DIM, D_ROOT, NT_ROOT, 0);
    hmma_gemm<1><<<dim3(NT0,     N_ROWS / 128), 256>>>(h0bf, wt0,    p0p, nullptr, H0,    D0,     NT0,     0);
    hmma_gemm<1><<<dim3(NT1,     N_ROWS / 128), 256>>>(h1bf, wt1,    p1p, nullptr, H1,    D1,     NT1,     0);

    // 4. picked logits, LSE+CE, final scalar
    picked_kernel<<<N_ROWS, 128>>>(logits, targets, head_kernel, scale0, scale1);
    lse_kernel<<<N_ROWS, 96>>>();
    final_kernel<<<1, 1024>>>(targets, out);
}